// round 5
// baseline (speedup 1.0000x reference)
#include <cuda_runtime.h>

#define NB   128   // batch
#define ND   32    // dims
#define NP   16384 // N0*N1 pairs
#define NCTA 148   // one CTA per SM, balanced pair split
#define THREADS 512
#define TILE 56    // pairs staged in smem per phase (111 = 56 + 55)
#define GROUPS 4
#define PSTRIDE 33 // 32 num + 1 den

__device__ float g_partial[NCTA * NB * PSTRIDE];

// ---------------------------------------------------------------------------
// Fused kernel: per-tile coefficient compute (warp-per-pair, lane-per-dim,
// coalesced) directly into SMEM, then FMA-bound accumulation
// (thread = batch x pair-group), fixed-order reductions throughout.
// ---------------------------------------------------------------------------
__global__ __launch_bounds__(THREADS, 1)
void gmm_main(const float* __restrict__ X,   const float* __restrict__ t_ptr,
              const float* __restrict__ Mu0, const float* __restrict__ Mu1,
              const float* __restrict__ S0,  const float* __restrict__ S1,
              const float* __restrict__ Lam)
{
    __shared__ float s_p2[TILE * ND];
    __shared__ float s_p1[TILE * ND];
    __shared__ float s_pk[TILE * ND];
    __shared__ float s_pc[TILE * ND];
    __shared__ float s_p0[TILE];
    __shared__ float s_lam[TILE];
    __shared__ float s_red[NB * PSTRIDE];

    const int tid  = threadIdx.x;
    const int wid  = tid >> 5;
    const int lane = tid & 31;
    const int g    = tid >> 7;        // pair group 0..3
    const int b    = tid & (NB - 1);  // batch

    // balanced contiguous pair range for this CTA
    const int cta     = blockIdx.x;
    const int basecnt = NP / NCTA;            // 110
    const int rem     = NP - basecnt * NCTA;  // 104
    const int start   = cta * basecnt + (cta < rem ? cta : rem);
    const int end     = start + basecnt + (cta < rem ? 1 : 0);

    const float t     = t_ptr[0];
    const float omt   = 1.0f - t;
    const float e2    = 0.25f;     // eps^2 (eps = 0.5)
    const float e4    = 0.0625f;   // eps^4
    const float tt    = t * t;
    const float omt2  = omt * omt;
    const float t2omt = 2.0f * t * omt;
    const float e2tot = e2 * t * omt;

    // X row for this thread's batch in registers
    float4 x[8];
    {
        const float4* xg = (const float4*)(X + b * ND);
        #pragma unroll
        for (int q = 0; q < 8; q++) x[q] = xg[q];
    }

    float  den = 0.0f;
    float4 num[8];
    #pragma unroll
    for (int q = 0; q < 8; q++) num[q] = make_float4(0.f, 0.f, 0.f, 0.f);

    for (int base = start; base < end; base += TILE) {
        const int np = min(TILE, end - base);

        // ---- coefficient phase: warp per pair, lane per dim (coalesced) ----
        for (int p = wid; p < np; p += THREADS / 32) {
            const int ij = base + p;
            const int i  = ij >> 7;
            const int j  = ij & 127;

            const float lam = Lam[ij];   // issue early; consumed by lane 0 only

            const float s0 = S0[i * ND + lane];
            const float s1 = S1[j * ND + lane];
            const float Ds = sqrtf(fmaf(4.0f * s0, s1, e4));
            const float Cs = 0.5f * (Ds - e2);
            const float Sigma = omt2 * s0 + tt * s1 + t2omt * Cs + e2tot;
            const float St = (t * s1 + omt * Cs) - (omt * s0 + t * Cs) - e2 * t;

            const float mu0 = Mu0[i * ND + lane];
            const float mu1 = Mu1[j * ND + lane];
            const float mut = fmaf(t, mu1, omt * mu0);

            const float inv = __fdividef(1.0f, Sigma);
            const float K   = St * inv;
            const float a   = -0.5f * inv;

            s_p2[p * ND + lane] = a;
            s_p1[p * ND + lane] = inv * mut;
            s_pk[p * ND + lane] = K;
            s_pc[p * ND + lane] = (mu1 - mu0) - K * mut;

            float p0 = fmaf(a * mut, mut, -0.5f * __logf(Sigma));
            #pragma unroll
            for (int off = 16; off; off >>= 1)
                p0 += __shfl_xor_sync(0xFFFFFFFFu, p0, off);
            if (lane == 0) { s_p0[p] = p0; s_lam[p] = lam; }
        }
        __syncthreads();

        // ---- accumulate phase: group g handles pairs p = g, g+4, ... ----
        for (int p = g; p < np; p += GROUPS) {
            const float4* a4 = (const float4*)(s_p2 + p * ND);
            const float4* b4 = (const float4*)(s_p1 + p * ND);

            float lw0 = s_p0[p], lw1 = 0.f, lw2 = 0.f, lw3 = 0.f;
            #pragma unroll
            for (int q = 0; q < 8; q++) {
                const float4 av = a4[q];
                const float4 bv = b4[q];
                lw0 = fmaf(fmaf(av.x, x[q].x, bv.x), x[q].x, lw0);
                lw1 = fmaf(fmaf(av.y, x[q].y, bv.y), x[q].y, lw1);
                lw2 = fmaf(fmaf(av.z, x[q].z, bv.z), x[q].z, lw2);
                lw3 = fmaf(fmaf(av.w, x[q].w, bv.w), x[q].w, lw3);
            }
            float logw = (lw0 + lw1) + (lw2 + lw3);
            logw = fminf(fmaxf(logw, -50.0f), 50.0f);
            const float w = __expf(logw) * s_lam[p];
            den += w;

            const float4* k4 = (const float4*)(s_pk + p * ND);
            const float4* c4 = (const float4*)(s_pc + p * ND);
            #pragma unroll
            for (int q = 0; q < 8; q++) {
                const float4 kv = k4[q];
                const float4 cv = c4[q];
                num[q].x = fmaf(fmaf(kv.x, x[q].x, cv.x), w, num[q].x);
                num[q].y = fmaf(fmaf(kv.y, x[q].y, cv.y), w, num[q].y);
                num[q].z = fmaf(fmaf(kv.z, x[q].z, cv.z), w, num[q].z);
                num[q].w = fmaf(fmaf(kv.w, x[q].w, cv.w), w, num[q].w);
            }
        }
        __syncthreads();
    }

    // ---- group combine: fixed order g = 0,1,2,3 (deterministic) ----
    for (int gg = 0; gg < GROUPS; gg++) {
        if (g == gg) {
            float* my = s_red + b * PSTRIDE;
            if (gg == 0) {
                #pragma unroll
                for (int q = 0; q < 8; q++) {
                    my[4*q+0] = num[q].x; my[4*q+1] = num[q].y;
                    my[4*q+2] = num[q].z; my[4*q+3] = num[q].w;
                }
                my[32] = den;
            } else {
                #pragma unroll
                for (int q = 0; q < 8; q++) {
                    my[4*q+0] += num[q].x; my[4*q+1] += num[q].y;
                    my[4*q+2] += num[q].z; my[4*q+3] += num[q].w;
                }
                my[32] += den;
            }
        }
        __syncthreads();
    }

    // write this CTA's partial (num[32] + den per batch) to global
    float* gp = g_partial + (size_t)cta * NB * PSTRIDE;
    for (int k = tid; k < NB * PSTRIDE; k += THREADS)
        gp[k] = s_red[k];
}

// ---------------------------------------------------------------------------
// Final reduce over the 148 CTA partials, divide num/den
// ---------------------------------------------------------------------------
__global__ void reduce_kernel(float* __restrict__ out)
{
    const int idx = blockIdx.x * blockDim.x + threadIdx.x;  // 0..4095
    if (idx >= NB * ND) return;
    const int b = idx / ND;
    const int n = idx - b * ND;

    float num = 0.0f, den = 0.0f;
    #pragma unroll 4
    for (int c = 0; c < NCTA; c++) {
        const float* p = g_partial + (size_t)c * NB * PSTRIDE + b * PSTRIDE;
        num += p[n];
        den += p[32];
    }
    out[idx] = num / den;
}

// ---------------------------------------------------------------------------
extern "C" void kernel_launch(void* const* d_in, const int* in_sizes, int n_in,
                              void* d_out, int out_size)
{
    const float* X   = (const float*)d_in[0];
    const float* t   = (const float*)d_in[1];
    const float* Mu0 = (const float*)d_in[2];
    const float* Mu1 = (const float*)d_in[3];
    const float* S0  = (const float*)d_in[4];
    const float* S1  = (const float*)d_in[5];
    const float* Lam = (const float*)d_in[6];
    float* out = (float*)d_out;

    gmm_main<<<NCTA, THREADS>>>(X, t, Mu0, Mu1, S0, S1, Lam);
    reduce_kernel<<<(NB * ND + 255) / 256, 256>>>(out);
}

// round 6
// speedup vs baseline: 1.7863x; 1.7863x over previous
#include <cuda_runtime.h>

#define NB   128   // batch
#define ND   32    // dims
#define NP   16384 // N0*N1 pairs
#define NCTA 148   // one CTA per SM, balanced pair split
#define THREADS 512
#define TILE 56    // pairs staged in smem per phase (111 = 56 + 55)
#define GROUPS 4
#define PSTRIDE 33 // 32 num + 1 den

__device__ float g_partial[NCTA * NB * PSTRIDE];

// ---------------------------------------------------------------------------
// Fused kernel: per-tile coefficient compute (warp-per-pair, lane-per-dim,
// coalesced) directly into SMEM, then FMA-bound accumulation
// (thread = batch x pair-group), fixed-order reductions throughout.
// (UNCHANGED from R5 — passed @ ~27us; this round only fixes the reduce.)
// ---------------------------------------------------------------------------
__global__ __launch_bounds__(THREADS, 1)
void gmm_main(const float* __restrict__ X,   const float* __restrict__ t_ptr,
              const float* __restrict__ Mu0, const float* __restrict__ Mu1,
              const float* __restrict__ S0,  const float* __restrict__ S1,
              const float* __restrict__ Lam)
{
    __shared__ float s_p2[TILE * ND];
    __shared__ float s_p1[TILE * ND];
    __shared__ float s_pk[TILE * ND];
    __shared__ float s_pc[TILE * ND];
    __shared__ float s_p0[TILE];
    __shared__ float s_lam[TILE];
    __shared__ float s_red[NB * PSTRIDE];

    const int tid  = threadIdx.x;
    const int wid  = tid >> 5;
    const int lane = tid & 31;
    const int g    = tid >> 7;        // pair group 0..3
    const int b    = tid & (NB - 1);  // batch

    // balanced contiguous pair range for this CTA
    const int cta     = blockIdx.x;
    const int basecnt = NP / NCTA;            // 110
    const int rem     = NP - basecnt * NCTA;  // 104
    const int start   = cta * basecnt + (cta < rem ? cta : rem);
    const int end     = start + basecnt + (cta < rem ? 1 : 0);

    const float t     = t_ptr[0];
    const float omt   = 1.0f - t;
    const float e2    = 0.25f;     // eps^2 (eps = 0.5)
    const float e4    = 0.0625f;   // eps^4
    const float tt    = t * t;
    const float omt2  = omt * omt;
    const float t2omt = 2.0f * t * omt;
    const float e2tot = e2 * t * omt;

    // X row for this thread's batch in registers
    float4 x[8];
    {
        const float4* xg = (const float4*)(X + b * ND);
        #pragma unroll
        for (int q = 0; q < 8; q++) x[q] = xg[q];
    }

    float  den = 0.0f;
    float4 num[8];
    #pragma unroll
    for (int q = 0; q < 8; q++) num[q] = make_float4(0.f, 0.f, 0.f, 0.f);

    for (int base = start; base < end; base += TILE) {
        const int np = min(TILE, end - base);

        // ---- coefficient phase: warp per pair, lane per dim (coalesced) ----
        for (int p = wid; p < np; p += THREADS / 32) {
            const int ij = base + p;
            const int i  = ij >> 7;
            const int j  = ij & 127;

            const float lam = Lam[ij];   // issue early; consumed by lane 0 only

            const float s0 = S0[i * ND + lane];
            const float s1 = S1[j * ND + lane];
            const float Ds = sqrtf(fmaf(4.0f * s0, s1, e4));
            const float Cs = 0.5f * (Ds - e2);
            const float Sigma = omt2 * s0 + tt * s1 + t2omt * Cs + e2tot;
            const float St = (t * s1 + omt * Cs) - (omt * s0 + t * Cs) - e2 * t;

            const float mu0 = Mu0[i * ND + lane];
            const float mu1 = Mu1[j * ND + lane];
            const float mut = fmaf(t, mu1, omt * mu0);

            const float inv = __fdividef(1.0f, Sigma);
            const float K   = St * inv;
            const float a   = -0.5f * inv;

            s_p2[p * ND + lane] = a;
            s_p1[p * ND + lane] = inv * mut;
            s_pk[p * ND + lane] = K;
            s_pc[p * ND + lane] = (mu1 - mu0) - K * mut;

            float p0 = fmaf(a * mut, mut, -0.5f * __logf(Sigma));
            #pragma unroll
            for (int off = 16; off; off >>= 1)
                p0 += __shfl_xor_sync(0xFFFFFFFFu, p0, off);
            if (lane == 0) { s_p0[p] = p0; s_lam[p] = lam; }
        }
        __syncthreads();

        // ---- accumulate phase: group g handles pairs p = g, g+4, ... ----
        for (int p = g; p < np; p += GROUPS) {
            const float4* a4 = (const float4*)(s_p2 + p * ND);
            const float4* b4 = (const float4*)(s_p1 + p * ND);

            float lw0 = s_p0[p], lw1 = 0.f, lw2 = 0.f, lw3 = 0.f;
            #pragma unroll
            for (int q = 0; q < 8; q++) {
                const float4 av = a4[q];
                const float4 bv = b4[q];
                lw0 = fmaf(fmaf(av.x, x[q].x, bv.x), x[q].x, lw0);
                lw1 = fmaf(fmaf(av.y, x[q].y, bv.y), x[q].y, lw1);
                lw2 = fmaf(fmaf(av.z, x[q].z, bv.z), x[q].z, lw2);
                lw3 = fmaf(fmaf(av.w, x[q].w, bv.w), x[q].w, lw3);
            }
            float logw = (lw0 + lw1) + (lw2 + lw3);
            logw = fminf(fmaxf(logw, -50.0f), 50.0f);
            const float w = __expf(logw) * s_lam[p];
            den += w;

            const float4* k4 = (const float4*)(s_pk + p * ND);
            const float4* c4 = (const float4*)(s_pc + p * ND);
            #pragma unroll
            for (int q = 0; q < 8; q++) {
                const float4 kv = k4[q];
                const float4 cv = c4[q];
                num[q].x = fmaf(fmaf(kv.x, x[q].x, cv.x), w, num[q].x);
                num[q].y = fmaf(fmaf(kv.y, x[q].y, cv.y), w, num[q].y);
                num[q].z = fmaf(fmaf(kv.z, x[q].z, cv.z), w, num[q].z);
                num[q].w = fmaf(fmaf(kv.w, x[q].w, cv.w), w, num[q].w);
            }
        }
        __syncthreads();
    }

    // ---- group combine: fixed order g = 0,1,2,3 (deterministic) ----
    for (int gg = 0; gg < GROUPS; gg++) {
        if (g == gg) {
            float* my = s_red + b * PSTRIDE;
            if (gg == 0) {
                #pragma unroll
                for (int q = 0; q < 8; q++) {
                    my[4*q+0] = num[q].x; my[4*q+1] = num[q].y;
                    my[4*q+2] = num[q].z; my[4*q+3] = num[q].w;
                }
                my[32] = den;
            } else {
                #pragma unroll
                for (int q = 0; q < 8; q++) {
                    my[4*q+0] += num[q].x; my[4*q+1] += num[q].y;
                    my[4*q+2] += num[q].z; my[4*q+3] += num[q].w;
                }
                my[32] += den;
            }
        }
        __syncthreads();
    }

    // write this CTA's partial (num[32] + den per batch) to global
    float* gp = g_partial + (size_t)cta * NB * PSTRIDE;
    for (int k = tid; k < NB * PSTRIDE; k += THREADS)
        gp[k] = s_red[k];
}

// ---------------------------------------------------------------------------
// Final reduce: CTA per batch, warp per output element, lanes strided over
// the 148 CTA partials (high MLP), butterfly shfl (fixed order -> determ.)
// ---------------------------------------------------------------------------
__global__ __launch_bounds__(256, 1)
void reduce_kernel(float* __restrict__ out)
{
    __shared__ float s_sum[PSTRIDE];

    const int b    = blockIdx.x;           // batch
    const int w    = threadIdx.x >> 5;     // warp 0..7
    const int lane = threadIdx.x & 31;

    for (int n = w; n < PSTRIDE; n += 8) {
        float acc = 0.0f;
        // lanes cover c = lane, lane+32, ... : up to 5 independent loads
        #pragma unroll
        for (int i = 0; i < 5; i++) {
            const int c = lane + 32 * i;
            if (c < NCTA)
                acc += g_partial[(size_t)c * NB * PSTRIDE + b * PSTRIDE + n];
        }
        #pragma unroll
        for (int off = 16; off; off >>= 1)
            acc += __shfl_xor_sync(0xFFFFFFFFu, acc, off);
        if (lane == 0) s_sum[n] = acc;
    }
    __syncthreads();

    if (threadIdx.x < ND)
        out[b * ND + threadIdx.x] = s_sum[threadIdx.x] / s_sum[32];
}

// ---------------------------------------------------------------------------
extern "C" void kernel_launch(void* const* d_in, const int* in_sizes, int n_in,
                              void* d_out, int out_size)
{
    const float* X   = (const float*)d_in[0];
    const float* t   = (const float*)d_in[1];
    const float* Mu0 = (const float*)d_in[2];
    const float* Mu1 = (const float*)d_in[3];
    const float* S0  = (const float*)d_in[4];
    const float* S1  = (const float*)d_in[5];
    const float* Lam = (const float*)d_in[6];
    float* out = (float*)d_out;

    gmm_main<<<NCTA, THREADS>>>(X, t, Mu0, Mu1, S0, S1, Lam);
    reduce_kernel<<<NB, 256>>>(out);
}

// round 7
// speedup vs baseline: 1.8017x; 1.0087x over previous
#include <cuda_runtime.h>

#define NB   128   // batch
#define ND   32    // dims
#define NP   16384 // N0*N1 pairs
#define NCTA 148   // one CTA per SM, balanced pair split
#define THREADS 512
#define TILE 56    // pairs staged in smem per phase (111 = 56 + 55)
#define GROUPS 4
#define PSTRIDE 33 // 32 num + 1 den

typedef unsigned long long u64;

__device__ float g_partial[NCTA * NB * PSTRIDE];

// ---- packed f32x2 helpers (Blackwell FFMA2: only reachable via PTX) ----
__device__ __forceinline__ u64 fma2(u64 a, u64 b, u64 c) {
    u64 d;
    asm("fma.rn.f32x2 %0, %1, %2, %3;" : "=l"(d) : "l"(a), "l"(b), "l"(c));
    return d;
}
__device__ __forceinline__ u64 pack2(float lo, float hi) {
    u64 d;
    asm("mov.b64 %0, {%1, %2};" : "=l"(d) : "f"(lo), "f"(hi));
    return d;
}
__device__ __forceinline__ void unpack2(u64 v, float& lo, float& hi) {
    asm("mov.b64 {%0, %1}, %2;" : "=f"(lo), "=f"(hi) : "l"(v));
}

// ---------------------------------------------------------------------------
// Fused kernel: per-tile coefficient compute (warp-per-pair, lane-per-dim)
// into SMEM, then packed-f32x2 FMA accumulation (thread = batch x pair-group).
// Fixed-order reductions -> deterministic.
// ---------------------------------------------------------------------------
__global__ __launch_bounds__(THREADS, 1)
void gmm_main(const float* __restrict__ X,   const float* __restrict__ t_ptr,
              const float* __restrict__ Mu0, const float* __restrict__ Mu1,
              const float* __restrict__ S0,  const float* __restrict__ S1,
              const float* __restrict__ Lam)
{
    __shared__ float s_p2[TILE * ND];
    __shared__ float s_p1[TILE * ND];
    __shared__ float s_pk[TILE * ND];
    __shared__ float s_pc[TILE * ND];
    __shared__ float s_p0[TILE];
    __shared__ float s_lam[TILE];
    __shared__ float s_red[NB * PSTRIDE];

    const int tid  = threadIdx.x;
    const int wid  = tid >> 5;
    const int lane = tid & 31;
    const int g    = tid >> 7;        // pair group 0..3
    const int b    = tid & (NB - 1);  // batch

    // balanced contiguous pair range for this CTA
    const int cta     = blockIdx.x;
    const int basecnt = NP / NCTA;            // 110
    const int rem     = NP - basecnt * NCTA;  // 104
    const int start   = cta * basecnt + (cta < rem ? cta : rem);
    const int end     = start + basecnt + (cta < rem ? 1 : 0);

    const float t     = t_ptr[0];
    const float omt   = 1.0f - t;
    const float e2    = 0.25f;     // eps^2 (eps = 0.5)
    const float e4    = 0.0625f;   // eps^4
    const float tt    = t * t;
    const float omt2  = omt * omt;
    const float t2omt = 2.0f * t * omt;
    const float e2tot = e2 * t * omt;

    // X row for this thread's batch: 16 packed f32x2 in registers
    u64 xq[16];
    {
        const ulonglong2* xg = (const ulonglong2*)(X + b * ND);
        #pragma unroll
        for (int q = 0; q < 8; q++) {
            const ulonglong2 v = xg[q];
            xq[2*q]   = v.x;
            xq[2*q+1] = v.y;
        }
    }

    float den = 0.0f;
    u64 numq[16];
    #pragma unroll
    for (int q = 0; q < 16; q++) numq[q] = 0ull;   // bits(0,0) == (0.f,0.f)

    for (int base = start; base < end; base += TILE) {
        const int np = min(TILE, end - base);

        // ---- coefficient phase: warp per pair, lane per dim (coalesced) ----
        for (int p = wid; p < np; p += THREADS / 32) {
            const int ij = base + p;
            const int i  = ij >> 7;
            const int j  = ij & 127;

            const float lam = Lam[ij];

            const float s0 = S0[i * ND + lane];
            const float s1 = S1[j * ND + lane];
            const float Ds = sqrtf(fmaf(4.0f * s0, s1, e4));
            const float Cs = 0.5f * (Ds - e2);
            const float Sigma = omt2 * s0 + tt * s1 + t2omt * Cs + e2tot;
            const float St = (t * s1 + omt * Cs) - (omt * s0 + t * Cs) - e2 * t;

            const float mu0 = Mu0[i * ND + lane];
            const float mu1 = Mu1[j * ND + lane];
            const float mut = fmaf(t, mu1, omt * mu0);

            const float inv = __fdividef(1.0f, Sigma);
            const float K   = St * inv;
            const float a   = -0.5f * inv;

            s_p2[p * ND + lane] = a;
            s_p1[p * ND + lane] = inv * mut;
            s_pk[p * ND + lane] = K;
            s_pc[p * ND + lane] = (mu1 - mu0) - K * mut;

            float p0 = fmaf(a * mut, mut, -0.5f * __logf(Sigma));
            #pragma unroll
            for (int off = 16; off; off >>= 1)
                p0 += __shfl_xor_sync(0xFFFFFFFFu, p0, off);
            if (lane == 0) { s_p0[p] = p0; s_lam[p] = lam; }
        }
        __syncthreads();

        // ---- accumulate phase (packed f32x2): group g takes p = g, g+4,... ----
        for (int p = g; p < np; p += GROUPS) {
            const ulonglong2* A2 = (const ulonglong2*)(s_p2 + p * ND);
            const ulonglong2* B2 = (const ulonglong2*)(s_p1 + p * ND);

            u64 l0 = pack2(s_p0[p], 0.0f), l1 = 0ull, l2 = 0ull, l3 = 0ull;
            #pragma unroll
            for (int q = 0; q < 8; q++) {
                const ulonglong2 av = A2[q];
                const ulonglong2 bv = B2[q];
                const u64 t0 = fma2(av.x, xq[2*q],   bv.x);
                const u64 t1 = fma2(av.y, xq[2*q+1], bv.y);
                if (q & 1) {
                    l2 = fma2(t0, xq[2*q],   l2);
                    l3 = fma2(t1, xq[2*q+1], l3);
                } else {
                    l0 = fma2(t0, xq[2*q],   l0);
                    l1 = fma2(t1, xq[2*q+1], l1);
                }
            }
            float f0, f1, f2, f3, f4, f5, f6, f7;
            unpack2(l0, f0, f1); unpack2(l1, f2, f3);
            unpack2(l2, f4, f5); unpack2(l3, f6, f7);
            float logw = ((f0 + f1) + (f2 + f3)) + ((f4 + f5) + (f6 + f7));
            logw = fminf(fmaxf(logw, -50.0f), 50.0f);
            const float w = __expf(logw) * s_lam[p];
            den += w;
            const u64 w2 = pack2(w, w);

            const ulonglong2* K2 = (const ulonglong2*)(s_pk + p * ND);
            const ulonglong2* C2 = (const ulonglong2*)(s_pc + p * ND);
            #pragma unroll
            for (int q = 0; q < 8; q++) {
                const ulonglong2 kv = K2[q];
                const ulonglong2 cv = C2[q];
                const u64 t0 = fma2(kv.x, xq[2*q],   cv.x);
                const u64 t1 = fma2(kv.y, xq[2*q+1], cv.y);
                numq[2*q]   = fma2(t0, w2, numq[2*q]);
                numq[2*q+1] = fma2(t1, w2, numq[2*q+1]);
            }
        }
        __syncthreads();
    }

    // ---- group combine: fixed order g = 0,1,2,3 (deterministic) ----
    for (int gg = 0; gg < GROUPS; gg++) {
        if (g == gg) {
            float* my = s_red + b * PSTRIDE;
            if (gg == 0) {
                #pragma unroll
                for (int q = 0; q < 16; q++) {
                    float lo, hi;
                    unpack2(numq[q], lo, hi);
                    my[2*q]   = lo;
                    my[2*q+1] = hi;
                }
                my[32] = den;
            } else {
                #pragma unroll
                for (int q = 0; q < 16; q++) {
                    float lo, hi;
                    unpack2(numq[q], lo, hi);
                    my[2*q]   += lo;
                    my[2*q+1] += hi;
                }
                my[32] += den;
            }
        }
        __syncthreads();
    }

    // write this CTA's partial (num[32] + den per batch) to global
    float* gp = g_partial + (size_t)cta * NB * PSTRIDE;
    for (int k = tid; k < NB * PSTRIDE; k += THREADS)
        gp[k] = s_red[k];
}

// ---------------------------------------------------------------------------
// Final reduce v3: CTA per batch, 16 warps; warp w sums outputs n = w, w+16,
// (and n = 32 on all warps, stored by warp 0). All loads independent and
// fully unrolled -> one DRAM/L2 latency round. Butterfly shfl = fixed order.
// ---------------------------------------------------------------------------
__global__ __launch_bounds__(512, 1)
void reduce_kernel(float* __restrict__ out)
{
    __shared__ float s_sum[PSTRIDE];

    const int b    = blockIdx.x;
    const int w    = threadIdx.x >> 5;
    const int lane = threadIdx.x & 31;
    const float* bp = g_partial + b * PSTRIDE;

    float acc[3] = {0.f, 0.f, 0.f};
    const int nn[3] = {w, w + 16, 32};
    #pragma unroll
    for (int r = 0; r < 3; r++) {
        #pragma unroll
        for (int i = 0; i < 5; i++) {
            const int c = lane + 32 * i;
            if (c < NCTA)
                acc[r] += bp[(size_t)c * NB * PSTRIDE + nn[r]];
        }
    }
    #pragma unroll
    for (int r = 0; r < 3; r++) {
        #pragma unroll
        for (int off = 16; off; off >>= 1)
            acc[r] += __shfl_xor_sync(0xFFFFFFFFu, acc[r], off);
    }
    if (lane == 0) {
        s_sum[nn[0]] = acc[0];
        s_sum[nn[1]] = acc[1];
        if (w == 0) s_sum[32] = acc[2];
    }
    __syncthreads();

    if (threadIdx.x < ND)
        out[b * ND + threadIdx.x] = s_sum[threadIdx.x] / s_sum[32];
}

// ---------------------------------------------------------------------------
extern "C" void kernel_launch(void* const* d_in, const int* in_sizes, int n_in,
                              void* d_out, int out_size)
{
    const float* X   = (const float*)d_in[0];
    const float* t   = (const float*)d_in[1];
    const float* Mu0 = (const float*)d_in[2];
    const float* Mu1 = (const float*)d_in[3];
    const float* S0  = (const float*)d_in[4];
    const float* S1  = (const float*)d_in[5];
    const float* Lam = (const float*)d_in[6];
    float* out = (float*)d_out;

    gmm_main<<<NCTA, THREADS>>>(X, t, Mu0, Mu1, S0, S1, Lam);
    reduce_kernel<<<NB, 512>>>(out);
}